// round 3
// baseline (speedup 1.0000x reference)
#include <cuda_runtime.h>
#include <cuda_fp16.h>
#include <cstdint>

#define NMAX 200000
#define EMAX 6400000
#define GMAX 1024

// Persistent scratch (device globals; no allocation)
__device__ float  d_ACC [NMAX * 12];           // node accumulator, padded rows (48B)
__device__ __half d_Adst[NMAX * 24];           // [f0..f9,s0..s9,pad] per node (48B rows)
__device__ __half d_Asrc[NMAX * 24];
__device__ float  d_sums[GMAX * 12];           // pooled sums, padded rows
__device__ float  d_cnt [GMAX];
__device__ int    d_is64[2];                   // [0]=edge_index is int64, [1]=batch is int64

// ---------------------------------------------------------------------------
// dtype detection: int64 data has zero high words; int32 data interpreted as
// u64 has random nonzero high words (node ids / graph ids in the sampled range).
__global__ void k_detect(const unsigned long long* __restrict__ ei,
                         const unsigned long long* __restrict__ bt, int nbase)
{
    __shared__ int anyhi[2];
    int t = threadIdx.x;
    if (t < 2) anyhi[t] = 0;
    __syncthreads();
    if (t < 128) {
        int a = 0;
        #pragma unroll
        for (int k = 0; k < 4; k++) a |= ((ei[1024 + t * 4 + k] >> 32) != 0ULL);
        if (a) atomicOr(&anyhi[0], 1);
    } else {
        int tt = t - 128, a = 0;
        #pragma unroll
        for (int k = 0; k < 4; k++) a |= ((bt[nbase + tt * 4 + k] >> 32) != 0ULL);
        if (a) atomicOr(&anyhi[1], 1);
    }
    __syncthreads();
    if (t == 0) { d_is64[0] = anyhi[0] ? 0 : 1; d_is64[1] = anyhi[1] ? 0 : 1; }
}

// ---------------------------------------------------------------------------
// Shared helper: from h[10] compute fp16 A-tables and write ACC = h.
__device__ __forceinline__ void write_node_tables(
    int i, const float h[10],
    const float* __restrict__ s_fW, const float* __restrict__ s_fb,
    const float* __restrict__ s_sW, const float* __restrict__ s_sb)
{
    float adf[10], asf[10], ads[10], ass[10];
    #pragma unroll
    for (int j = 0; j < 10; j++) { adf[j] = s_fb[j]; ads[j] = s_sb[j]; asf[j] = 0.f; ass[j] = 0.f; }
    #pragma unroll
    for (int k = 0; k < 10; k++) {
        float hk = h[k];
        #pragma unroll
        for (int j = 0; j < 10; j++) {
            adf[j] += s_fW[j * 23 + k]      * hk;
            asf[j] += s_fW[j * 23 + 10 + k] * hk;
            ads[j] += s_sW[j * 23 + k]      * hk;
            ass[j] += s_sW[j * 23 + 10 + k] * hk;
        }
    }
    unsigned rd[12], rs[12];
    #pragma unroll
    for (int j = 0; j < 5; j++) {
        __half2 a = __floats2half2_rn(adf[2*j], adf[2*j+1]); rd[j]     = *(unsigned*)&a;
        __half2 b = __floats2half2_rn(ads[2*j], ads[2*j+1]); rd[5 + j] = *(unsigned*)&b;
        __half2 c = __floats2half2_rn(asf[2*j], asf[2*j+1]); rs[j]     = *(unsigned*)&c;
        __half2 d = __floats2half2_rn(ass[2*j], ass[2*j+1]); rs[5 + j] = *(unsigned*)&d;
    }
    rd[10] = rd[11] = rs[10] = rs[11] = 0u;
    uint4* od = (uint4*)(d_Adst + (long)i * 24);
    od[0] = make_uint4(rd[0], rd[1], rd[2], rd[3]);
    od[1] = make_uint4(rd[4], rd[5], rd[6], rd[7]);
    od[2] = make_uint4(rd[8], rd[9], rd[10], rd[11]);
    uint4* os = (uint4*)(d_Asrc + (long)i * 24);
    os[0] = make_uint4(rs[0], rs[1], rs[2], rs[3]);
    os[1] = make_uint4(rs[4], rs[5], rs[6], rs[7]);
    os[2] = make_uint4(rs[8], rs[9], rs[10], rs[11]);
    float4* a4 = (float4*)(d_ACC + (long)i * 12);
    a4[0] = make_float4(h[0], h[1], h[2], h[3]);
    a4[1] = make_float4(h[4], h[5], h[6], h[7]);
    a4[2] = make_float4(h[8], h[9], 0.f, 0.f);
}

// ---------------------------------------------------------------------------
// Kernel 1: pre-linear + relu, build layer-1 A-tables, init ACC=h, zero pools.
__global__ void k_pre_t1(const float* __restrict__ x,
                         const float* __restrict__ pW, const float* __restrict__ pb,
                         const float* __restrict__ fW, const float* __restrict__ fb,
                         const float* __restrict__ sW, const float* __restrict__ sb, int n)
{
    __shared__ float s_fW[230], s_sW[230], s_pW[30], s_fb[10], s_sb[10], s_pb[10];
    int t = threadIdx.x;
    for (int k = t; k < 230; k += 256) { s_fW[k] = fW[k]; s_sW[k] = sW[k]; }
    if (t < 30) s_pW[t] = pW[t];
    if (t < 10) { s_fb[t] = fb[t]; s_sb[t] = sb[t]; s_pb[t] = pb[t]; }
    int gid = blockIdx.x * blockDim.x + t;
    if (gid < GMAX * 12) d_sums[gid] = 0.f;
    if (gid < GMAX)      d_cnt[gid]  = 0.f;
    __syncthreads();
    if (gid >= n) return;
    float x0 = x[3 * (long)gid], x1 = x[3 * (long)gid + 1], x2 = x[3 * (long)gid + 2];
    float h[10];
    #pragma unroll
    for (int j = 0; j < 10; j++)
        h[j] = fmaxf(s_pW[j*3] * x0 + s_pW[j*3+1] * x1 + s_pW[j*3+2] * x2 + s_pb[j], 0.f);
    write_node_tables(gid, h, s_fW, s_fb, s_sW, s_sb);
}

// Kernel 3: relu(ACC) -> layer-2 A-tables, ACC=h.
__global__ void k_t2(const float* __restrict__ fW, const float* __restrict__ fb,
                     const float* __restrict__ sW, const float* __restrict__ sb, int n)
{
    __shared__ float s_fW[230], s_sW[230], s_fb[10], s_sb[10];
    int t = threadIdx.x;
    for (int k = t; k < 230; k += 256) { s_fW[k] = fW[k]; s_sW[k] = sW[k]; }
    if (t < 10) { s_fb[t] = fb[t]; s_sb[t] = sb[t]; }
    __syncthreads();
    int gid = blockIdx.x * blockDim.x + t;
    if (gid >= n) return;
    const float4* a4 = (const float4*)(d_ACC + (long)gid * 12);
    float4 v0 = a4[0], v1 = a4[1], v2 = a4[2];
    float h[10] = { fmaxf(v0.x,0.f), fmaxf(v0.y,0.f), fmaxf(v0.z,0.f), fmaxf(v0.w,0.f),
                    fmaxf(v1.x,0.f), fmaxf(v1.y,0.f), fmaxf(v1.z,0.f), fmaxf(v1.w,0.f),
                    fmaxf(v2.x,0.f), fmaxf(v2.y,0.f) };
    write_node_tables(gid, h, s_fW, s_fb, s_sW, s_sb);
}

// ---------------------------------------------------------------------------
// Edge kernel: gather fp16 A-tables, add edge term, gated message, vector red.
__global__ void __launch_bounds__(256, 2)
k_edge(const void* __restrict__ eip, const float* __restrict__ ea,
       const float* __restrict__ fW, const float* __restrict__ sW, int E)
{
    const int is64 = d_is64[0];
    float wf0[10], wf1[10], wf2[10], ws0[10], ws1[10], ws2[10];
    #pragma unroll
    for (int j = 0; j < 10; j++) {
        wf0[j] = fW[j*23+20]; wf1[j] = fW[j*23+21]; wf2[j] = fW[j*23+22];
        ws0[j] = sW[j*23+20]; ws1[j] = sW[j*23+21]; ws2[j] = sW[j*23+22];
    }
    const long long* ei64 = (const long long*)eip;
    const int*       ei32 = (const int*)eip;
    long stride = (long)gridDim.x * blockDim.x;
    for (long e = (long)blockIdx.x * blockDim.x + threadIdx.x; e < E; e += stride) {
        int s, d;
        if (is64) { s = (int)ei64[e]; d = (int)ei64[E + e]; }
        else      { s = ei32[e];      d = ei32[E + e]; }
        const float* ep = ea + 3 * e;
        float e0 = ep[0], e1 = ep[1], e2 = ep[2];

        const uint4* pd = (const uint4*)(d_Adst + (long)d * 24);
        const uint4* ps = (const uint4*)(d_Asrc + (long)s * 24);
        uint4 da = pd[0], db = pd[1]; uint2 dc = ((const uint2*)pd)[4];
        uint4 sa = ps[0], sb = ps[1]; uint2 sc = ((const uint2*)ps)[4];

        unsigned du[5] = {da.x, da.y, da.z, da.w, db.x};
        unsigned dv[5] = {db.y, db.z, db.w, dc.x, dc.y};
        unsigned su[5] = {sa.x, sa.y, sa.z, sa.w, sb.x};
        unsigned sv[5] = {sb.y, sb.z, sb.w, sc.x, sc.y};

        float f[10], g[10];
        #pragma unroll
        for (int j = 0; j < 5; j++) {
            __half2 hf = __hadd2(*(__half2*)&du[j], *(__half2*)&su[j]);
            float2 ff = __half22float2(hf); f[2*j] = ff.x; f[2*j+1] = ff.y;
            __half2 hg = __hadd2(*(__half2*)&dv[j], *(__half2*)&sv[j]);
            float2 gg = __half22float2(hg); g[2*j] = gg.x; g[2*j+1] = gg.y;
        }
        float m[10];
        #pragma unroll
        for (int j = 0; j < 10; j++) {
            float fv = f[j] + wf0[j]*e0 + wf1[j]*e1 + wf2[j]*e2;   // bias folded in Adst
            float gv = g[j] + ws0[j]*e0 + ws1[j]*e1 + ws2[j]*e2;
            float sig = __fdividef(1.f, 1.f + __expf(-fv));
            float sp  = fmaxf(gv, 0.f) + __logf(1.f + __expf(-fabsf(gv)));
            m[j] = sig * sp;
        }
        float* base = d_ACC + (long)d * 12;
        asm volatile("red.global.add.v4.f32 [%0], {%1,%2,%3,%4};"
                     :: "l"(base),     "f"(m[0]), "f"(m[1]), "f"(m[2]), "f"(m[3]) : "memory");
        asm volatile("red.global.add.v4.f32 [%0], {%1,%2,%3,%4};"
                     :: "l"(base + 4), "f"(m[4]), "f"(m[5]), "f"(m[6]), "f"(m[7]) : "memory");
        asm volatile("red.global.add.v2.f32 [%0], {%1,%2};"
                     :: "l"(base + 8), "f"(m[8]), "f"(m[9]) : "memory");
    }
}

// ---------------------------------------------------------------------------
// Pooling: relu(ACC) summed per graph. batch is sorted -> warp-uniform fast path.
__global__ void k_pool(const void* __restrict__ bp, int n)
{
    int i = blockIdx.x * blockDim.x + threadIdx.x;
    unsigned mask = __ballot_sync(0xffffffffu, i < n);
    if (i >= n) return;
    const int is64 = d_is64[1];
    int b = is64 ? (int)((const long long*)bp)[i] : ((const int*)bp)[i];
    const float4* a4 = (const float4*)(d_ACC + (long)i * 12);
    float4 v0 = a4[0], v1 = a4[1], v2 = a4[2];
    float h[10] = { fmaxf(v0.x,0.f), fmaxf(v0.y,0.f), fmaxf(v0.z,0.f), fmaxf(v0.w,0.f),
                    fmaxf(v1.x,0.f), fmaxf(v1.y,0.f), fmaxf(v1.z,0.f), fmaxf(v1.w,0.f),
                    fmaxf(v2.x,0.f), fmaxf(v2.y,0.f) };
    int b0 = __shfl_sync(mask, b, 0);
    if (mask == 0xffffffffu && __all_sync(mask, b == b0)) {
        #pragma unroll
        for (int j = 0; j < 10; j++) {
            float v = h[j];
            v += __shfl_xor_sync(0xffffffffu, v, 16);
            v += __shfl_xor_sync(0xffffffffu, v, 8);
            v += __shfl_xor_sync(0xffffffffu, v, 4);
            v += __shfl_xor_sync(0xffffffffu, v, 2);
            v += __shfl_xor_sync(0xffffffffu, v, 1);
            h[j] = v;
        }
        if ((threadIdx.x & 31) == 0) {
            float* base = d_sums + b * 12;
            asm volatile("red.global.add.v4.f32 [%0], {%1,%2,%3,%4};"
                         :: "l"(base),     "f"(h[0]), "f"(h[1]), "f"(h[2]), "f"(h[3]) : "memory");
            asm volatile("red.global.add.v4.f32 [%0], {%1,%2,%3,%4};"
                         :: "l"(base + 4), "f"(h[4]), "f"(h[5]), "f"(h[6]), "f"(h[7]) : "memory");
            asm volatile("red.global.add.v2.f32 [%0], {%1,%2};"
                         :: "l"(base + 8), "f"(h[8]), "f"(h[9]) : "memory");
            atomicAdd(d_cnt + b, 32.f);
        }
    } else {
        #pragma unroll
        for (int j = 0; j < 10; j++) atomicAdd(d_sums + b * 12 + j, h[j]);
        atomicAdd(d_cnt + b, 1.f);
    }
}

// ---------------------------------------------------------------------------
// Final MLP: one block per graph (128 threads).
__global__ void k_mlp(const float* __restrict__ w1, const float* __restrict__ b1,
                      const float* __restrict__ w2, const float* __restrict__ b2,
                      const float* __restrict__ ow, const float* __restrict__ ob,
                      float* __restrict__ out, int G)
{
    int g = blockIdx.x, t = threadIdx.x;
    __shared__ float gin[10], y1[128], y2[128];
    if (t < 10) {
        float c = d_cnt[g];
        gin[t] = d_sums[g * 12 + t] / fmaxf(c, 1.f);
    }
    __syncthreads();
    {
        float a = b1[t];
        #pragma unroll
        for (int k = 0; k < 10; k++) a += w1[t * 10 + k] * gin[k];
        y1[t] = fmaxf(a, 0.f);
    }
    __syncthreads();
    {
        float a = b2[t];
        #pragma unroll 8
        for (int k = 0; k < 128; k++) a += w2[t * 128 + k] * y1[k];
        y2[t] = fmaxf(a, 0.f);
    }
    __syncthreads();
    int w = t >> 5, l = t & 31;
    if (w < 3) {
        float p = 0.f;
        #pragma unroll
        for (int q = 0; q < 4; q++) p += ow[w * 128 + q * 32 + l] * y2[q * 32 + l];
        p += __shfl_xor_sync(0xffffffffu, p, 16);
        p += __shfl_xor_sync(0xffffffffu, p, 8);
        p += __shfl_xor_sync(0xffffffffu, p, 4);
        p += __shfl_xor_sync(0xffffffffu, p, 2);
        p += __shfl_xor_sync(0xffffffffu, p, 1);
        if (l == 0) out[g * 3 + w] = p + ob[w];
    }
}

// ---------------------------------------------------------------------------
extern "C" void kernel_launch(void* const* d_in, const int* in_sizes, int n_in,
                              void* d_out, int out_size)
{
    const float* x    = (const float*)d_in[0];
    const void*  ei   = d_in[1];
    const float* ea   = (const float*)d_in[2];
    const void*  bt   = d_in[3];
    const float* pW   = (const float*)d_in[4];
    const float* pb   = (const float*)d_in[5];
    const float* f1W  = (const float*)d_in[6];
    const float* f1b  = (const float*)d_in[7];
    const float* s1W  = (const float*)d_in[8];
    const float* s1b  = (const float*)d_in[9];
    const float* f2W  = (const float*)d_in[10];
    const float* f2b  = (const float*)d_in[11];
    const float* s2W  = (const float*)d_in[12];
    const float* s2b  = (const float*)d_in[13];
    const float* fc1W = (const float*)d_in[14];
    const float* fc1b = (const float*)d_in[15];
    const float* fc2W = (const float*)d_in[16];
    const float* fc2b = (const float*)d_in[17];
    const float* oW   = (const float*)d_in[18];
    const float* obv  = (const float*)d_in[19];

    int n = in_sizes[0] / 3;  if (n > NMAX) n = NMAX;
    int E = in_sizes[2] / 3;  if (E > EMAX) E = EMAX;
    int G = out_size / 3;     if (G > GMAX) G = GMAX;

    k_detect<<<1, 256>>>((const unsigned long long*)ei, (const unsigned long long*)bt, n / 4);

    int nb = (n + 255) / 256;
    k_pre_t1<<<nb, 256>>>(x, pW, pb, f1W, f1b, s1W, s1b, n);
    k_edge<<<592, 256>>>(ei, ea, f1W, s1W, E);
    k_t2<<<nb, 256>>>(f2W, f2b, s2W, s2b, n);
    k_edge<<<592, 256>>>(ei, ea, f2W, s2W, E);
    k_pool<<<nb, 256>>>(bt, n);
    k_mlp<<<G, 128>>>(fc1W, fc1b, fc2W, fc2b, oW, obv, (float*)d_out, G);
}

// round 7
// speedup vs baseline: 1.0327x; 1.0327x over previous
#include <cuda_runtime.h>
#include <cuda_fp16.h>
#include <cstdint>

#define NMAX 200000
#define EMAX 6400000
#define GMAX 1024
#define AGGS 16   // halves per aggregation row (32B, sector-aligned)

// Persistent scratch (device globals; no allocation)
__device__ float  d_H   [NMAX * 12];           // node state h (f32), 48B rows
__device__ __half d_AGG [NMAX * AGGS];         // fp16 message accumulator, 32B rows
__device__ __half d_Adst[NMAX * 24];           // [f0..f9,s0..s9,pad] per node (48B rows)
__device__ __half d_Asrc[NMAX * 24];
__device__ int2   d_EIDX[EMAX];                // interleaved (src,dst) int32
__device__ float  d_sums[GMAX * 12];
__device__ float  d_cnt [GMAX];
__device__ int    d_is64[2];

// ---------------------------------------------------------------------------
// dtype detection: int64 data has zero high words.
__global__ void k_detect(const unsigned long long* __restrict__ ei,
                         const unsigned long long* __restrict__ bt, int nbase)
{
    __shared__ int anyhi[2];
    int t = threadIdx.x;
    if (t < 2) anyhi[t] = 0;
    __syncthreads();
    if (t < 128) {
        int a = 0;
        #pragma unroll
        for (int k = 0; k < 4; k++) a |= ((ei[1024 + t * 4 + k] >> 32) != 0ULL);
        if (a) atomicOr(&anyhi[0], 1);
    } else {
        int tt = t - 128, a = 0;
        #pragma unroll
        for (int k = 0; k < 4; k++) a |= ((bt[nbase + tt * 4 + k] >> 32) != 0ULL);
        if (a) atomicOr(&anyhi[1], 1);
    }
    __syncthreads();
    if (t == 0) { d_is64[0] = anyhi[0] ? 0 : 1; d_is64[1] = anyhi[1] ? 0 : 1; }
}

// ---------------------------------------------------------------------------
// From h[10] compute fp16 A-tables (bias folded into Adst) and store d_H = h.
__device__ __forceinline__ void write_node_tables(
    int i, const float h[10],
    const float* __restrict__ s_fW, const float* __restrict__ s_fb,
    const float* __restrict__ s_sW, const float* __restrict__ s_sb)
{
    float adf[10], asf[10], ads[10], ass[10];
    #pragma unroll
    for (int j = 0; j < 10; j++) { adf[j] = s_fb[j]; ads[j] = s_sb[j]; asf[j] = 0.f; ass[j] = 0.f; }
    #pragma unroll
    for (int k = 0; k < 10; k++) {
        float hk = h[k];
        #pragma unroll
        for (int j = 0; j < 10; j++) {
            adf[j] += s_fW[j * 23 + k]      * hk;
            asf[j] += s_fW[j * 23 + 10 + k] * hk;
            ads[j] += s_sW[j * 23 + k]      * hk;
            ass[j] += s_sW[j * 23 + 10 + k] * hk;
        }
    }
    unsigned rd[12], rs[12];
    #pragma unroll
    for (int j = 0; j < 5; j++) {
        __half2 a = __floats2half2_rn(adf[2*j], adf[2*j+1]); rd[j]     = *(unsigned*)&a;
        __half2 b = __floats2half2_rn(ads[2*j], ads[2*j+1]); rd[5 + j] = *(unsigned*)&b;
        __half2 c = __floats2half2_rn(asf[2*j], asf[2*j+1]); rs[j]     = *(unsigned*)&c;
        __half2 d = __floats2half2_rn(ass[2*j], ass[2*j+1]); rs[5 + j] = *(unsigned*)&d;
    }
    rd[10] = rd[11] = rs[10] = rs[11] = 0u;
    uint4* od = (uint4*)(d_Adst + (long)i * 24);
    od[0] = make_uint4(rd[0], rd[1], rd[2], rd[3]);
    od[1] = make_uint4(rd[4], rd[5], rd[6], rd[7]);
    od[2] = make_uint4(rd[8], rd[9], rd[10], rd[11]);
    uint4* os = (uint4*)(d_Asrc + (long)i * 24);
    os[0] = make_uint4(rs[0], rs[1], rs[2], rs[3]);
    os[1] = make_uint4(rs[4], rs[5], rs[6], rs[7]);
    os[2] = make_uint4(rs[8], rs[9], rs[10], rs[11]);
    float4* a4 = (float4*)(d_H + (long)i * 12);
    a4[0] = make_float4(h[0], h[1], h[2], h[3]);
    a4[1] = make_float4(h[4], h[5], h[6], h[7]);
    a4[2] = make_float4(h[8], h[9], 0.f, 0.f);
}

// ---------------------------------------------------------------------------
// Combined kernel: node blocks do pre-linear + layer-1 tables + zero AGG/pools;
// remaining blocks convert edge_index to interleaved int2.
__global__ void k_pre_t1(const float* __restrict__ x,
                         const float* __restrict__ pW, const float* __restrict__ pb,
                         const float* __restrict__ fW, const float* __restrict__ fb,
                         const float* __restrict__ sW, const float* __restrict__ sb,
                         const void* __restrict__ eip, int n, int nbN, int E)
{
    int t = threadIdx.x;
    if ((int)blockIdx.x >= nbN) {
        // ---- edge-index prep: 1024 edges per block ----
        const int is64 = d_is64[0];
        long base = (long)(blockIdx.x - nbN) * 1024;
        const long long* ei64 = (const long long*)eip;
        const int*       ei32 = (const int*)eip;
        #pragma unroll
        for (int k = 0; k < 4; k++) {
            long e = base + k * 256 + t;
            if (e < E) {
                int s, d;
                if (is64) { s = (int)ei64[e]; d = (int)ei64[E + e]; }
                else      { s = ei32[e];      d = ei32[E + e]; }
                d_EIDX[e] = make_int2(s, d);
            }
        }
        return;
    }
    __shared__ float s_fW[230], s_sW[230], s_pW[30], s_fb[10], s_sb[10], s_pb[10];
    for (int k = t; k < 230; k += 256) { s_fW[k] = fW[k]; s_sW[k] = sW[k]; }
    if (t < 30) s_pW[t] = pW[t];
    if (t < 10) { s_fb[t] = fb[t]; s_sb[t] = sb[t]; s_pb[t] = pb[t]; }
    int gid = blockIdx.x * blockDim.x + t;
    if (gid < GMAX * 12) d_sums[gid] = 0.f;
    if (gid < GMAX)      d_cnt[gid]  = 0.f;
    __syncthreads();
    if (gid >= n) return;
    // zero this node's aggregation row (32B)
    uint4* z = (uint4*)(d_AGG + (long)gid * AGGS);
    z[0] = make_uint4(0,0,0,0); z[1] = make_uint4(0,0,0,0);
    float x0 = x[3 * (long)gid], x1 = x[3 * (long)gid + 1], x2 = x[3 * (long)gid + 2];
    float h[10];
    #pragma unroll
    for (int j = 0; j < 10; j++)
        h[j] = fmaxf(s_pW[j*3] * x0 + s_pW[j*3+1] * x1 + s_pW[j*3+2] * x2 + s_pb[j], 0.f);
    write_node_tables(gid, h, s_fW, s_fb, s_sW, s_sb);
}

// ---------------------------------------------------------------------------
// Read fp16 aggregate, h = relu(h + agg), re-zero AGG, build layer-2 tables.
__global__ void k_t2(const float* __restrict__ fW, const float* __restrict__ fb,
                     const float* __restrict__ sW, const float* __restrict__ sb, int n)
{
    __shared__ float s_fW[230], s_sW[230], s_fb[10], s_sb[10];
    int t = threadIdx.x;
    for (int k = t; k < 230; k += 256) { s_fW[k] = fW[k]; s_sW[k] = sW[k]; }
    if (t < 10) { s_fb[t] = fb[t]; s_sb[t] = sb[t]; }
    __syncthreads();
    int gid = blockIdx.x * blockDim.x + t;
    if (gid >= n) return;
    __half* arow = d_AGG + (long)gid * AGGS;
    uint4 ua = *(const uint4*)arow;
    unsigned u4 = ((const unsigned*)arow)[4];
    ((uint4*)arow)[0] = make_uint4(0,0,0,0);
    ((uint4*)arow)[1] = make_uint4(0,0,0,0);
    float ag[10];
    {
        unsigned uu[5] = {ua.x, ua.y, ua.z, ua.w, u4};
        #pragma unroll
        for (int j = 0; j < 5; j++) {
            float2 f2 = __half22float2(*(__half2*)&uu[j]);
            ag[2*j] = f2.x; ag[2*j+1] = f2.y;
        }
    }
    const float4* a4 = (const float4*)(d_H + (long)gid * 12);
    float4 v0 = a4[0], v1 = a4[1], v2 = a4[2];
    float hv[12] = { v0.x, v0.y, v0.z, v0.w, v1.x, v1.y, v1.z, v1.w, v2.x, v2.y, 0.f, 0.f };
    float h[10];
    #pragma unroll
    for (int j = 0; j < 10; j++) h[j] = fmaxf(hv[j] + ag[j], 0.f);
    write_node_tables(gid, h, s_fW, s_fb, s_sW, s_sb);
}

// ---------------------------------------------------------------------------
// Edge kernel: gather fp16 A-tables, add edge term, gated message, fp16 red.
__global__ void __launch_bounds__(256)
k_edge(const float* __restrict__ ea,
       const float* __restrict__ fW, const float* __restrict__ sW, int E)
{
    __shared__ float sw[64];     // [k*10+j]: k=0..2 -> Wf edge cols, k=3..5 -> Ws
    int t = threadIdx.x;
    if (t < 60) {
        int k = t / 10, j = t % 10;
        sw[t] = (k < 3) ? fW[j*23 + 20 + k] : sW[j*23 + 20 + (k - 3)];
    }
    __syncthreads();
    long e = (long)blockIdx.x * 256 + t;
    if (e >= E) return;
    int2 sd = d_EIDX[e];
    int s = sd.x, d = sd.y;
    const float* ep = ea + 3 * e;
    float e0 = ep[0], e1 = ep[1], e2 = ep[2];

    const uint4* pd = (const uint4*)(d_Adst + (long)d * 24);
    const uint4* ps = (const uint4*)(d_Asrc + (long)s * 24);
    uint4 da = pd[0], db = pd[1]; uint2 dc = ((const uint2*)pd)[4];
    uint4 sa = ps[0], sb = ps[1]; uint2 sc = ((const uint2*)ps)[4];

    unsigned du[5] = {da.x, da.y, da.z, da.w, db.x};
    unsigned dv[5] = {db.y, db.z, db.w, dc.x, dc.y};
    unsigned su[5] = {sa.x, sa.y, sa.z, sa.w, sb.x};
    unsigned sv[5] = {sb.y, sb.z, sb.w, sc.x, sc.y};

    float f[10], g[10];
    #pragma unroll
    for (int j = 0; j < 5; j++) {
        __half2 hf = __hadd2(*(__half2*)&du[j], *(__half2*)&su[j]);
        float2 ff = __half22float2(hf); f[2*j] = ff.x; f[2*j+1] = ff.y;
        __half2 hg = __hadd2(*(__half2*)&dv[j], *(__half2*)&sv[j]);
        float2 gg = __half22float2(hg); g[2*j] = gg.x; g[2*j+1] = gg.y;
    }
    unsigned p[5];
    #pragma unroll
    for (int j = 0; j < 5; j++) {
        float m2[2];
        #pragma unroll
        for (int q = 0; q < 2; q++) {
            int jj = 2*j + q;
            float fv = f[jj] + sw[jj]*e0 + sw[10+jj]*e1 + sw[20+jj]*e2;
            float gv = g[jj] + sw[30+jj]*e0 + sw[40+jj]*e1 + sw[50+jj]*e2;
            float sig = __fdividef(1.f, 1.f + __expf(-fv));
            float sp  = fmaxf(gv, 0.f) + __logf(1.f + __expf(-fabsf(gv)));
            m2[q] = sig * sp;
        }
        __half2 hm = __floats2half2_rn(m2[0], m2[1]);
        p[j] = *(unsigned*)&hm;
    }
    __half* base = d_AGG + (long)d * AGGS;
    asm volatile("red.global.add.noftz.v4.f16x2 [%0], {%1,%2,%3,%4};"
                 :: "l"(base), "r"(p[0]), "r"(p[1]), "r"(p[2]), "r"(p[3]) : "memory");
    asm volatile("red.global.add.noftz.f16x2 [%0], %1;"
                 :: "l"(base + 8), "r"(p[4]) : "memory");
}

// ---------------------------------------------------------------------------
// Pooling: relu(h + agg) summed per graph; sorted batch -> warp-uniform path.
__global__ void k_pool(const void* __restrict__ bp, int n)
{
    int i = blockIdx.x * blockDim.x + threadIdx.x;
    unsigned mask = __ballot_sync(0xffffffffu, i < n);
    if (i >= n) return;
    const int is64 = d_is64[1];
    int b = is64 ? (int)((const long long*)bp)[i] : ((const int*)bp)[i];

    const __half* arow = d_AGG + (long)i * AGGS;
    uint4 ua = *(const uint4*)arow;
    unsigned u4 = ((const unsigned*)arow)[4];
    float ag[10];
    {
        unsigned uu[5] = {ua.x, ua.y, ua.z, ua.w, u4};
        #pragma unroll
        for (int j = 0; j < 5; j++) {
            float2 f2 = __half22float2(*(__half2*)&uu[j]);
            ag[2*j] = f2.x; ag[2*j+1] = f2.y;
        }
    }
    const float4* a4 = (const float4*)(d_H + (long)i * 12);
    float4 v0 = a4[0], v1 = a4[1], v2 = a4[2];
    float hv[10] = { v0.x, v0.y, v0.z, v0.w, v1.x, v1.y, v1.z, v1.w, v2.x, v2.y };
    float h[10];
    #pragma unroll
    for (int j = 0; j < 10; j++) h[j] = fmaxf(hv[j] + ag[j], 0.f);

    int b0 = __shfl_sync(mask, b, 0);
    if (mask == 0xffffffffu && __all_sync(mask, b == b0)) {
        #pragma unroll
        for (int j = 0; j < 10; j++) {
            float v = h[j];
            v += __shfl_xor_sync(0xffffffffu, v, 16);
            v += __shfl_xor_sync(0xffffffffu, v, 8);
            v += __shfl_xor_sync(0xffffffffu, v, 4);
            v += __shfl_xor_sync(0xffffffffu, v, 2);
            v += __shfl_xor_sync(0xffffffffu, v, 1);
            h[j] = v;
        }
        if ((threadIdx.x & 31) == 0) {
            float* base = d_sums + b * 12;
            asm volatile("red.global.add.v4.f32 [%0], {%1,%2,%3,%4};"
                         :: "l"(base),     "f"(h[0]), "f"(h[1]), "f"(h[2]), "f"(h[3]) : "memory");
            asm volatile("red.global.add.v4.f32 [%0], {%1,%2,%3,%4};"
                         :: "l"(base + 4), "f"(h[4]), "f"(h[5]), "f"(h[6]), "f"(h[7]) : "memory");
            asm volatile("red.global.add.v2.f32 [%0], {%1,%2};"
                         :: "l"(base + 8), "f"(h[8]), "f"(h[9]) : "memory");
            atomicAdd(d_cnt + b, 32.f);
        }
    } else {
        #pragma unroll
        for (int j = 0; j < 10; j++) atomicAdd(d_sums + b * 12 + j, h[j]);
        atomicAdd(d_cnt + b, 1.f);
    }
}

// ---------------------------------------------------------------------------
// Final MLP: one block per graph (128 threads).
__global__ void k_mlp(const float* __restrict__ w1, const float* __restrict__ b1,
                      const float* __restrict__ w2, const float* __restrict__ b2,
                      const float* __restrict__ ow, const float* __restrict__ ob,
                      float* __restrict__ out, int G)
{
    int g = blockIdx.x, t = threadIdx.x;
    __shared__ float gin[10], y1[128], y2[128];
    if (t < 10) {
        float c = d_cnt[g];
        gin[t] = d_sums[g * 12 + t] / fmaxf(c, 1.f);
    }
    __syncthreads();
    {
        float a = b1[t];
        #pragma unroll
        for (int k = 0; k < 10; k++) a += w1[t * 10 + k] * gin[k];
        y1[t] = fmaxf(a, 0.f);
    }
    __syncthreads();
    {
        float a = b2[t];
        #pragma unroll 8
        for (int k = 0; k < 128; k++) a += w2[t * 128 + k] * y1[k];
        y2[t] = fmaxf(a, 0.f);
    }
    __syncthreads();
    int w = t >> 5, l = t & 31;
    if (w < 3) {
        float p = 0.f;
        #pragma unroll
        for (int q = 0; q < 4; q++) p += ow[w * 128 + q * 32 + l] * y2[q * 32 + l];
        p += __shfl_xor_sync(0xffffffffu, p, 16);
        p += __shfl_xor_sync(0xffffffffu, p, 8);
        p += __shfl_xor_sync(0xffffffffu, p, 4);
        p += __shfl_xor_sync(0xffffffffu, p, 2);
        p += __shfl_xor_sync(0xffffffffu, p, 1);
        if (l == 0) out[g * 3 + w] = p + ob[w];
    }
}

// ---------------------------------------------------------------------------
extern "C" void kernel_launch(void* const* d_in, const int* in_sizes, int n_in,
                              void* d_out, int out_size)
{
    const float* x    = (const float*)d_in[0];
    const void*  ei   = d_in[1];
    const float* ea   = (const float*)d_in[2];
    const void*  bt   = d_in[3];
    const float* pW   = (const float*)d_in[4];
    const float* pb   = (const float*)d_in[5];
    const float* f1W  = (const float*)d_in[6];
    const float* f1b  = (const float*)d_in[7];
    const float* s1W  = (const float*)d_in[8];
    const float* s1b  = (const float*)d_in[9];
    const float* f2W  = (const float*)d_in[10];
    const float* f2b  = (const float*)d_in[11];
    const float* s2W  = (const float*)d_in[12];
    const float* s2b  = (const float*)d_in[13];
    const float* fc1W = (const float*)d_in[14];
    const float* fc1b = (const float*)d_in[15];
    const float* fc2W = (const float*)d_in[16];
    const float* fc2b = (const float*)d_in[17];
    const float* oW   = (const float*)d_in[18];
    const float* obv  = (const float*)d_in[19];

    int n = in_sizes[0] / 3;  if (n > NMAX) n = NMAX;
    int E = in_sizes[2] / 3;  if (E > EMAX) E = EMAX;
    int G = out_size / 3;     if (G > GMAX) G = GMAX;

    k_detect<<<1, 256>>>((const unsigned long long*)ei, (const unsigned long long*)bt, n / 4);

    int nbN = (n + 255) / 256;
    int nbP = (E + 1023) / 1024;
    int ebl = (E + 255) / 256;
    k_pre_t1<<<nbN + nbP, 256>>>(x, pW, pb, f1W, f1b, s1W, s1b, ei, n, nbN, E);
    k_edge<<<ebl, 256>>>(ea, f1W, s1W, E);
    k_t2<<<nbN, 256>>>(f2W, f2b, s2W, s2b, n);
    k_edge<<<ebl, 256>>>(ea, f2W, s2W, E);
    k_pool<<<nbN, 256>>>(bt, n);
    k_mlp<<<G, 128>>>(fc1W, fc1b, fc2W, fc2b, oW, obv, (float*)d_out, G);
}